// round 10
// baseline (speedup 1.0000x reference)
#include <cuda_runtime.h>
#include <cuda_fp16.h>
#include <cstdint>

#define LN_EPS 1e-5f

static constexpr int Fdim = 64;
static constexpr int Hdim = 128;

// cross-CTA combine scratch (written every launch before read; counter self-resets)
__device__ int d_partial[2048][128];
__device__ int d_counter[512];

// pack two floats as fp16x2: lo -> low half, hi -> high half
__device__ __forceinline__ uint32_t packh(float lo, float hi) {
    uint32_t r;
    asm("cvt.rn.f16x2.f32 %0, %1, %2;" : "=r"(r) : "f"(hi), "f"(lo));
    return r;
}

__device__ __forceinline__ void mma_f16(float c[4], const uint32_t a[4], const uint32_t b[2]) {
    asm volatile(
        "mma.sync.aligned.m16n8k16.row.col.f32.f16.f16.f32 "
        "{%0,%1,%2,%3}, {%4,%5,%6,%7}, {%8,%9}, {%0,%1,%2,%3};\n"
        : "+f"(c[0]), "+f"(c[1]), "+f"(c[2]), "+f"(c[3])
        : "r"(a[0]), "r"(a[1]), "r"(a[2]), "r"(a[3]), "r"(b[0]), "r"(b[1]));
}

// grid = 4N: CTA (n, qtr) owns 128 rows. 8 warps = 2 row-groups x 4 col-quarters;
// warp tile = 16 rows x 32 cols, B frags register-resident, 4 sweeps of 32 rows.
// LN stats combined across the 4 col-quarter warps via double-buffered smem.
// Pool: shuffle-free per-lane atomicMax into q-spread slab; last CTA of the
// batch combines partials, writes g, broadcasts g_exp.
extern "C" __global__ void __launch_bounds__(256, 2)
fused_kernel(const float* __restrict__ x, const int* __restrict__ mask,
             const float* __restrict__ W, const float* __restrict__ bias,
             const float* __restrict__ gamma, const float* __restrict__ beta,
             float* __restrict__ out, float* __restrict__ gout, int L)
{
    __shared__ uint2  Bfrag[4 * 16 * 32];      // 16 KB
    __shared__ int    gsm8[8][128];            // q-spread pooled max slab
    __shared__ int    gsm[128];
    __shared__ float2 sStat[2][2][4][16];      // [buf][rg][cq][row] = (sum, sq)
    __shared__ int    sIsLast;

    const int tid  = threadIdx.x;
    const int bidx = blockIdx.x;
    const int n    = bidx >> 2;
    const int qtr  = bidx & 3;

    // pack W into fp16 mma B-fragment order
    for (int idx = tid; idx < 4 * 16 * 32; idx += 256) {
        int lane = idx & 31;
        int t    = (idx >> 5) & 15;
        int ks   = idx >> 9;
        int qq = lane >> 2, ss = lane & 3;
        int h  = t * 8 + qq;
        int f0 = ks * 16 + ss * 2;
        float2 w01 = *reinterpret_cast<const float2*>(W + h * Fdim + f0);
        float2 w89 = *reinterpret_cast<const float2*>(W + h * Fdim + f0 + 8);
        uint2 v;
        v.x = packh(w01.x, w01.y);
        v.y = packh(w89.x, w89.y);
        Bfrag[idx] = v;
    }
    for (int i = tid; i < 8 * 128; i += 256) ((int*)gsm8)[i] = 0;
    __syncthreads();

    const int lane = tid & 31;
    const int warp = tid >> 5;
    const int q = lane >> 2, s = lane & 3;
    const int cq = warp & 3;        // column quarter: cols cq*32 .. cq*32+31
    const int rg = warp >> 2;       // row group within a 32-row sweep block

    // ---- hoist B fragments to registers (sweep-invariant) ----
    uint2 Breg[4][4];
    #pragma unroll
    for (int ks = 0; ks < 4; ks++)
        #pragma unroll
        for (int t = 0; t < 4; t++)
            Breg[ks][t] = Bfrag[ks * 512 + (cq * 4 + t) * 32 + lane];

    // ---- hoist bias/gamma/beta (per-lane columns) ----
    float2 bb[4], gg[4], bt[4];
    #pragma unroll
    for (int t = 0; t < 4; t++) {
        int col = cq * 32 + t * 8 + 2 * s;
        bb[t] = *reinterpret_cast<const float2*>(bias  + col);
        gg[t] = *reinterpret_cast<const float2*>(gamma + col);
        bt[t] = *reinterpret_cast<const float2*>(beta  + col);
    }

    int pb = 0;
    const int rbeg = qtr * 128;
    for (int rb = rbeg + rg * 16; rb < rbeg + 128; rb += 32, pb ^= 1) {
        const size_t rowA = (size_t)n * L + rb + q;
        const size_t rowB = rowA + 8;
        const float* xA = x + rowA * Fdim;
        const float* xB = x + rowB * Fdim;

        float acc[4][4];
        #pragma unroll
        for (int t = 0; t < 4; t++)
            acc[t][0] = acc[t][1] = acc[t][2] = acc[t][3] = 0.f;

        #pragma unroll
        for (int ks = 0; ks < 4; ks++) {
            const int f0 = ks * 16 + s * 2;
            float2 A0 = *reinterpret_cast<const float2*>(xA + f0);
            float2 A8 = *reinterpret_cast<const float2*>(xA + f0 + 8);
            float2 B0 = *reinterpret_cast<const float2*>(xB + f0);
            float2 B8 = *reinterpret_cast<const float2*>(xB + f0 + 8);
            uint32_t ah[4] = { packh(A0.x, A0.y), packh(B0.x, B0.y),
                               packh(A8.x, A8.y), packh(B8.x, B8.y) };
            #pragma unroll
            for (int t = 0; t < 4; t++) {
                uint32_t bh[2] = { Breg[ks][t].x, Breg[ks][t].y };
                mma_f16(acc[t], ah, bh);
            }
        }

        // bias + partial LN stats (this warp's 32 cols)
        float sumA = 0.f, sqA = 0.f, sumB = 0.f, sqB = 0.f;
        #pragma unroll
        for (int t = 0; t < 4; t++) {
            acc[t][0] += bb[t].x; acc[t][1] += bb[t].y;
            acc[t][2] += bb[t].x; acc[t][3] += bb[t].y;
            sumA += acc[t][0] + acc[t][1];
            sqA  += acc[t][0] * acc[t][0] + acc[t][1] * acc[t][1];
            sumB += acc[t][2] + acc[t][3];
            sqB  += acc[t][2] * acc[t][2] + acc[t][3] * acc[t][3];
        }
        #pragma unroll
        for (int m = 1; m <= 2; m <<= 1) {
            sumA += __shfl_xor_sync(0xffffffffu, sumA, m);
            sqA  += __shfl_xor_sync(0xffffffffu, sqA, m);
            sumB += __shfl_xor_sync(0xffffffffu, sumB, m);
            sqB  += __shfl_xor_sync(0xffffffffu, sqB, m);
        }
        if (s == 0) {
            sStat[pb][rg][cq][q]     = make_float2(sumA, sqA);
            sStat[pb][rg][cq][q + 8] = make_float2(sumB, sqB);
        }
        __syncthreads();
        float tsA = 0.f, tqA = 0.f, tsB = 0.f, tqB = 0.f;
        #pragma unroll
        for (int c = 0; c < 4; c++) {
            float2 a = sStat[pb][rg][c][q];
            float2 b = sStat[pb][rg][c][q + 8];
            tsA += a.x; tqA += a.y;
            tsB += b.x; tqB += b.y;
        }

        const float inv = 1.0f / (float)Hdim;
        float muA = tsA * inv, muB = tsB * inv;
        float rsA = rsqrtf(fmaxf(tqA * inv - muA * muA, 0.f) + LN_EPS);
        float rsB = rsqrtf(fmaxf(tqB * inv - muB * muB, 0.f) + LN_EPS);

        const bool mA = (mask[rowA] != 0);
        const bool mB = (mask[rowB] != 0);
        float* outA = out + rowA * (2 * Hdim);
        float* outB = out + rowB * (2 * Hdim);

        #pragma unroll
        for (int t = 0; t < 4; t++) {
            int col = cq * 32 + t * 8 + 2 * s;
            float yA0 = fmaxf((acc[t][0] - muA) * rsA * gg[t].x + bt[t].x, 0.f);
            float yA1 = fmaxf((acc[t][1] - muA) * rsA * gg[t].y + bt[t].y, 0.f);
            float yB0 = fmaxf((acc[t][2] - muB) * rsB * gg[t].x + bt[t].x, 0.f);
            float yB1 = fmaxf((acc[t][3] - muB) * rsB * gg[t].y + bt[t].y, 0.f);
            *reinterpret_cast<float2*>(outA + col) = make_float2(yA0, yA1);
            *reinterpret_cast<float2*>(outB + col) = make_float2(yB0, yB1);
            // shuffle-free pool: lane -> q-spread slab (max absorbs everything)
            float p0 = fmaxf(mA ? yA0 : 0.f, mB ? yB0 : 0.f);
            float p1 = fmaxf(mA ? yA1 : 0.f, mB ? yB1 : 0.f);
            atomicMax(&gsm8[q][col],     __float_as_int(p0));
            atomicMax(&gsm8[q][col + 1], __float_as_int(p1));
        }
    }
    __syncthreads();

    // ---- fold q-slab, publish partial; last of 4 CTAs finishes the batch ----
    if (tid < 128) {
        int r = gsm8[0][tid];
        #pragma unroll
        for (int k = 1; k < 8; k++) r = max(r, gsm8[k][tid]);
        d_partial[bidx][tid] = r;
    }
    __threadfence();
    __syncthreads();
    if (tid == 0) sIsLast = (atomicAdd(&d_counter[n], 1) == 3);
    __syncthreads();
    if (!sIsLast) return;

    __threadfence();
    if (tid < 128) {
        const int base = n << 2;
        int c = d_partial[base + 0][tid];
        c = max(c, d_partial[base + 1][tid]);
        c = max(c, d_partial[base + 2][tid]);
        c = max(c, d_partial[base + 3][tid]);
        gsm[tid] = c;
        gout[(size_t)n * Hdim + tid] = __int_as_float(c);
    }
    if (tid == 0) d_counter[n] = 0;   // self-reset for next graph replay
    __syncthreads();

    // broadcast g into out[n, :, H:2H] (whole batch, 8 warps)
    float4 gv;
    gv.x = __int_as_float(gsm[lane * 4 + 0]);
    gv.y = __int_as_float(gsm[lane * 4 + 1]);
    gv.z = __int_as_float(gsm[lane * 4 + 2]);
    gv.w = __int_as_float(gsm[lane * 4 + 3]);
    float* obase = out + (size_t)n * L * (2 * Hdim) + Hdim;
    for (int r = warp; r < L; r += 8)
        *reinterpret_cast<float4*>(obase + (size_t)r * (2 * Hdim) + lane * 4) = gv;
}

extern "C" void kernel_launch(void* const* d_in, const int* in_sizes, int n_in,
                              void* d_out, int out_size) {
    const float* x     = (const float*)d_in[0];
    const int*   mask  = (const int*)d_in[1];
    const float* W     = (const float*)d_in[2];
    const float* bias  = (const float*)d_in[3];
    const float* gamma = (const float*)d_in[4];
    const float* beta  = (const float*)d_in[5];
    float* out = (float*)d_out;

    const int NL = in_sizes[1];
    const long long ysize = (long long)NL * 2 * Hdim;
    const int N = (int)(((long long)out_size - ysize) / Hdim);
    const int L = NL / N;
    float* g = out + ysize;

    fused_kernel<<<4 * N, 256>>>(x, mask, W, bias, gamma, beta, out, g, L);
}

// round 11
// speedup vs baseline: 1.1249x; 1.1249x over previous
#include <cuda_runtime.h>
#include <cuda_fp16.h>
#include <cstdint>

#define LN_EPS 1e-5f

static constexpr int Fdim = 64;
static constexpr int Hdim = 128;

// smem layout (bytes): x-slab (512 rows x 272B pitch) | Bfrag | gsm
static constexpr int XPITCH   = 272;                 // 256B data + 16B pad (bank spread)
static constexpr int SM_XS    = 0;
static constexpr int SM_BFRAG = 512 * XPITCH;        // 139264
static constexpr int SM_GSM   = SM_BFRAG + 16384;    // 155648
static constexpr int SM_TOTAL = SM_GSM + 512;        // 156160

// pack two floats as fp16x2: lo -> low half, hi -> high half
__device__ __forceinline__ uint32_t packh(float lo, float hi) {
    uint32_t r;
    asm("cvt.rn.f16x2.f32 %0, %1, %2;" : "=r"(r) : "f"(hi), "f"(lo));
    return r;
}

__device__ __forceinline__ void mma_f16(float c[4], const uint32_t a[4], const uint32_t b[2]) {
    asm volatile(
        "mma.sync.aligned.m16n8k16.row.col.f32.f16.f16.f32 "
        "{%0,%1,%2,%3}, {%4,%5,%6,%7}, {%8,%9}, {%0,%1,%2,%3};\n"
        : "+f"(c[0]), "+f"(c[1]), "+f"(c[2]), "+f"(c[3])
        : "r"(a[0]), "r"(a[1]), "r"(a[2]), "r"(a[3]), "r"(b[0]), "r"(b[1]));
}

// One CTA per batch n; 16 warps x 16 rows = 256 rows/sweep, 2 sweeps (R7 structure).
// NEW: x staged to smem via cp.async at CTA start -> mainloop has zero DRAM reads.
extern "C" __global__ void __launch_bounds__(512, 1)
fused_kernel(const float* __restrict__ x, const int* __restrict__ mask,
             const float* __restrict__ W, const float* __restrict__ bias,
             const float* __restrict__ gamma, const float* __restrict__ beta,
             float* __restrict__ out, float* __restrict__ gout, int L)
{
    extern __shared__ char smem[];
    uint2* Bfrag = (uint2*)(smem + SM_BFRAG);   // [4 ks][16 t][32 lanes]
    int*   gsm   = (int*)(smem + SM_GSM);       // pooled max (int bits of floats >= 0)
    const uint32_t sb = (uint32_t)__cvta_generic_to_shared(smem);

    const int tid = threadIdx.x;
    const int n   = blockIdx.x;

    // ---- 1) async-stage the CTA's x slab (512 rows x 256B), fully coalesced ----
    {
        const char* gsrc = (const char*)(x + (size_t)n * L * Fdim);
        #pragma unroll
        for (int i = 0; i < 16; i++) {
            int id = tid + 512 * i;
            uint32_t dst = sb + SM_XS + (id >> 4) * XPITCH + (id & 15) * 16;
            asm volatile("cp.async.cg.shared.global [%0], [%1], 16;"
                         :: "r"(dst), "l"(gsrc + (size_t)id * 16) : "memory");
        }
        asm volatile("cp.async.commit_group;" ::: "memory");
    }

    // ---- 2) pack W into fp16 mma B-fragment order (overlaps the cp.async) ----
    for (int idx = tid; idx < 4 * 16 * 32; idx += 512) {
        int lane = idx & 31;
        int t    = (idx >> 5) & 15;
        int ks   = idx >> 9;
        int q = lane >> 2, s = lane & 3;
        int h  = t * 8 + q;
        int f0 = ks * 16 + s * 2;
        float2 w01 = *reinterpret_cast<const float2*>(W + h * Fdim + f0);
        float2 w89 = *reinterpret_cast<const float2*>(W + h * Fdim + f0 + 8);
        uint2 v;
        v.x = packh(w01.x, w01.y);
        v.y = packh(w89.x, w89.y);
        Bfrag[idx] = v;
    }
    if (tid < 128) gsm[tid] = 0;

    asm volatile("cp.async.wait_group 0;" ::: "memory");
    __syncthreads();

    const int lane = tid & 31;
    const int warp = tid >> 5;
    const int q = lane >> 2, s = lane & 3;

    for (int rb = warp * 16; rb < L; rb += 256) {
        const size_t rowA = (size_t)n * L + rb + q;       // global row (mask/out)
        const size_t rowB = rowA + 8;
        const char* xA = smem + SM_XS + (rb + q) * XPITCH;      // local row (x slab)
        const char* xB = xA + 8 * XPITCH;

        float acc[16][4];
        #pragma unroll
        for (int t = 0; t < 16; t++)
            acc[t][0] = acc[t][1] = acc[t][2] = acc[t][3] = 0.f;

        #pragma unroll
        for (int ks = 0; ks < 4; ks++) {
            const int fb = ks * 64 + s * 8;               // byte offset of f0
            float2 A0 = *reinterpret_cast<const float2*>(xA + fb);
            float2 A8 = *reinterpret_cast<const float2*>(xA + fb + 32);
            float2 B0 = *reinterpret_cast<const float2*>(xB + fb);
            float2 B8 = *reinterpret_cast<const float2*>(xB + fb + 32);
            uint32_t ah[4] = { packh(A0.x, A0.y), packh(B0.x, B0.y),
                               packh(A8.x, A8.y), packh(B8.x, B8.y) };
            const uint2* Bp = Bfrag + ks * 512 + lane;
            #pragma unroll
            for (int t = 0; t < 16; t++) {
                uint2 bv = Bp[t * 32];
                uint32_t bh[2] = { bv.x, bv.y };
                mma_f16(acc[t], ah, bh);
            }
        }

        #pragma unroll
        for (int t = 0; t < 16; t++) {
            float2 bb = *reinterpret_cast<const float2*>(bias + t * 8 + 2 * s);
            acc[t][0] += bb.x; acc[t][1] += bb.y;
            acc[t][2] += bb.x; acc[t][3] += bb.y;
        }

        float sumA = 0.f, sqA = 0.f, sumB = 0.f, sqB = 0.f;
        #pragma unroll
        for (int t = 0; t < 16; t++) {
            sumA += acc[t][0] + acc[t][1];
            sqA  += acc[t][0] * acc[t][0] + acc[t][1] * acc[t][1];
            sumB += acc[t][2] + acc[t][3];
            sqB  += acc[t][2] * acc[t][2] + acc[t][3] * acc[t][3];
        }
        #pragma unroll
        for (int m = 1; m <= 2; m <<= 1) {
            sumA += __shfl_xor_sync(0xffffffffu, sumA, m);
            sqA  += __shfl_xor_sync(0xffffffffu, sqA, m);
            sumB += __shfl_xor_sync(0xffffffffu, sumB, m);
            sqB  += __shfl_xor_sync(0xffffffffu, sqB, m);
        }
        const float inv = 1.0f / (float)Hdim;
        float muA = sumA * inv, muB = sumB * inv;
        float rsA = rsqrtf(fmaxf(sqA * inv - muA * muA, 0.f) + LN_EPS);
        float rsB = rsqrtf(fmaxf(sqB * inv - muB * muB, 0.f) + LN_EPS);

        const bool mA = (mask[rowA] != 0);
        const bool mB = (mask[rowB] != 0);
        float* outA = out + rowA * (2 * Hdim);
        float* outB = out + rowB * (2 * Hdim);

        float p0[16], p1[16];
        #pragma unroll
        for (int t = 0; t < 16; t++) {
            int col = t * 8 + 2 * s;
            float2 gg = *reinterpret_cast<const float2*>(gamma + col);
            float2 bt = *reinterpret_cast<const float2*>(beta + col);
            float yA0 = fmaxf((acc[t][0] - muA) * rsA * gg.x + bt.x, 0.f);
            float yA1 = fmaxf((acc[t][1] - muA) * rsA * gg.y + bt.y, 0.f);
            float yB0 = fmaxf((acc[t][2] - muB) * rsB * gg.x + bt.x, 0.f);
            float yB1 = fmaxf((acc[t][3] - muB) * rsB * gg.y + bt.y, 0.f);
            *reinterpret_cast<float2*>(outA + col) = make_float2(yA0, yA1);
            *reinterpret_cast<float2*>(outB + col) = make_float2(yB0, yB1);
            p0[t] = fmaxf(mA ? yA0 : 0.f, mB ? yB0 : 0.f);
            p1[t] = fmaxf(mA ? yA1 : 0.f, mB ? yB1 : 0.f);
        }

        #pragma unroll
        for (int t = 0; t < 16; t++) {
            #pragma unroll
            for (int m = 4; m <= 16; m <<= 1) {
                p0[t] = fmaxf(p0[t], __shfl_xor_sync(0xffffffffu, p0[t], m));
                p1[t] = fmaxf(p1[t], __shfl_xor_sync(0xffffffffu, p1[t], m));
            }
        }
        if (q == 0) {
            #pragma unroll
            for (int t = 0; t < 16; t++) {
                atomicMax(&gsm[t * 8 + 2 * s],     __float_as_int(p0[t]));
                atomicMax(&gsm[t * 8 + 2 * s + 1], __float_as_int(p1[t]));
            }
        }
    }
    __syncthreads();

    if (tid < 128)
        gout[(size_t)n * Hdim + tid] = __int_as_float(gsm[tid]);

    // broadcast g into out[n, :, H:2H] — 16 warps x float4 lanes
    float4 gv;
    gv.x = __int_as_float(gsm[lane * 4 + 0]);
    gv.y = __int_as_float(gsm[lane * 4 + 1]);
    gv.z = __int_as_float(gsm[lane * 4 + 2]);
    gv.w = __int_as_float(gsm[lane * 4 + 3]);
    float* obase = out + (size_t)n * L * (2 * Hdim) + Hdim;
    for (int r = warp; r < L; r += 16)
        *reinterpret_cast<float4*>(obase + (size_t)r * (2 * Hdim) + lane * 4) = gv;
}

extern "C" void kernel_launch(void* const* d_in, const int* in_sizes, int n_in,
                              void* d_out, int out_size) {
    const float* x     = (const float*)d_in[0];
    const int*   mask  = (const int*)d_in[1];
    const float* W     = (const float*)d_in[2];
    const float* bias  = (const float*)d_in[3];
    const float* gamma = (const float*)d_in[4];
    const float* beta  = (const float*)d_in[5];
    float* out = (float*)d_out;

    const int NL = in_sizes[1];
    const long long ysize = (long long)NL * 2 * Hdim;
    const int N = (int)(((long long)out_size - ysize) / Hdim);
    const int L = NL / N;
    float* g = out + ysize;

    cudaFuncSetAttribute(fused_kernel, cudaFuncAttributeMaxDynamicSharedMemorySize, SM_TOTAL);
    fused_kernel<<<N, 512, SM_TOTAL>>>(x, mask, W, bias, gamma, beta, out, g, L);
}

// round 12
// speedup vs baseline: 1.1658x; 1.0364x over previous
#include <cuda_runtime.h>
#include <cuda_fp16.h>
#include <cstdint>

#define LN_EPS 1e-5f

static constexpr int Fdim = 64;
static constexpr int Hdim = 128;

// pack two floats as fp16x2: lo -> low half, hi -> high half
__device__ __forceinline__ uint32_t packh(float lo, float hi) {
    uint32_t r;
    asm("cvt.rn.f16x2.f32 %0, %1, %2;" : "=r"(r) : "f"(hi), "f"(lo));
    return r;
}

__device__ __forceinline__ void mma_f16(float c[4], const uint32_t a[4], const uint32_t b[2]) {
    asm volatile(
        "mma.sync.aligned.m16n8k16.row.col.f32.f16.f16.f32 "
        "{%0,%1,%2,%3}, {%4,%5,%6,%7}, {%8,%9}, {%0,%1,%2,%3};\n"
        : "+f"(c[0]), "+f"(c[1]), "+f"(c[2]), "+f"(c[3])
        : "r"(a[0]), "r"(a[1]), "r"(a[2]), "r"(a[3]), "r"(b[0]), "r"(b[1]));
}

// One CTA per batch n; 16 warps x 16 rows = 256 rows/sweep, L/256 sweeps.
// Single-pass fp16 GEMM -> bias -> LN -> ReLU -> write y; pooled max via
// direct all-lane smem atomicMax (no shuffle tree); then g write + broadcast.
extern "C" __global__ void __launch_bounds__(512, 1)
fused_kernel(const float* __restrict__ x, const int* __restrict__ mask,
             const float* __restrict__ W, const float* __restrict__ bias,
             const float* __restrict__ gamma, const float* __restrict__ beta,
             float* __restrict__ out, float* __restrict__ gout, int L)
{
    __shared__ uint2 Bfrag[4 * 16 * 32];   // 16 KB
    __shared__ int   gsm[128];             // pooled max (int bits of floats >= 0)

    const int tid = threadIdx.x;
    const int n   = blockIdx.x;

    // pack W into fp16 mma B-fragment order
    for (int idx = tid; idx < 4 * 16 * 32; idx += 512) {
        int lane = idx & 31;
        int t    = (idx >> 5) & 15;
        int ks   = idx >> 9;
        int q = lane >> 2, s = lane & 3;
        int h  = t * 8 + q;
        int f0 = ks * 16 + s * 2;
        float2 w01 = *reinterpret_cast<const float2*>(W + h * Fdim + f0);
        float2 w89 = *reinterpret_cast<const float2*>(W + h * Fdim + f0 + 8);
        uint2 v;
        v.x = packh(w01.x, w01.y);
        v.y = packh(w89.x, w89.y);
        Bfrag[idx] = v;
    }
    if (tid < 128) gsm[tid] = 0;
    __syncthreads();

    const int lane = tid & 31;
    const int warp = tid >> 5;
    const int q = lane >> 2, s = lane & 3;

    for (int rb = warp * 16; rb < L; rb += 256) {
        const size_t rowA = (size_t)n * L + rb + q;
        const size_t rowB = rowA + 8;
        const float* xA = x + rowA * Fdim;
        const float* xB = x + rowB * Fdim;

        float acc[16][4];
        #pragma unroll
        for (int t = 0; t < 16; t++)
            acc[t][0] = acc[t][1] = acc[t][2] = acc[t][3] = 0.f;

        #pragma unroll
        for (int ks = 0; ks < 4; ks++) {
            const int f0 = ks * 16 + s * 2;
            float2 A0 = *reinterpret_cast<const float2*>(xA + f0);
            float2 A8 = *reinterpret_cast<const float2*>(xA + f0 + 8);
            float2 B0 = *reinterpret_cast<const float2*>(xB + f0);
            float2 B8 = *reinterpret_cast<const float2*>(xB + f0 + 8);
            uint32_t ah[4] = { packh(A0.x, A0.y), packh(B0.x, B0.y),
                               packh(A8.x, A8.y), packh(B8.x, B8.y) };
            const uint2* Bp = Bfrag + ks * 512 + lane;
            #pragma unroll
            for (int t = 0; t < 16; t++) {
                uint2 bv = Bp[t * 32];
                uint32_t bh[2] = { bv.x, bv.y };
                mma_f16(acc[t], ah, bh);
            }
        }

        #pragma unroll
        for (int t = 0; t < 16; t++) {
            float2 bb = *reinterpret_cast<const float2*>(bias + t * 8 + 2 * s);
            acc[t][0] += bb.x; acc[t][1] += bb.y;
            acc[t][2] += bb.x; acc[t][3] += bb.y;
        }

        float sumA = 0.f, sqA = 0.f, sumB = 0.f, sqB = 0.f;
        #pragma unroll
        for (int t = 0; t < 16; t++) {
            sumA += acc[t][0] + acc[t][1];
            sqA  += acc[t][0] * acc[t][0] + acc[t][1] * acc[t][1];
            sumB += acc[t][2] + acc[t][3];
            sqB  += acc[t][2] * acc[t][2] + acc[t][3] * acc[t][3];
        }
        #pragma unroll
        for (int m = 1; m <= 2; m <<= 1) {
            sumA += __shfl_xor_sync(0xffffffffu, sumA, m);
            sqA  += __shfl_xor_sync(0xffffffffu, sqA, m);
            sumB += __shfl_xor_sync(0xffffffffu, sumB, m);
            sqB  += __shfl_xor_sync(0xffffffffu, sqB, m);
        }
        const float inv = 1.0f / (float)Hdim;
        float muA = sumA * inv, muB = sumB * inv;
        float rsA = rsqrtf(fmaxf(sqA * inv - muA * muA, 0.f) + LN_EPS);
        float rsB = rsqrtf(fmaxf(sqB * inv - muB * muB, 0.f) + LN_EPS);

        const bool mA = (mask[rowA] != 0);
        const bool mB = (mask[rowB] != 0);
        float* outA = out + rowA * (2 * Hdim);
        float* outB = out + rowB * (2 * Hdim);

        #pragma unroll
        for (int t = 0; t < 16; t++) {
            int col = t * 8 + 2 * s;
            float2 gg = *reinterpret_cast<const float2*>(gamma + col);
            float2 bt = *reinterpret_cast<const float2*>(beta + col);
            float yA0 = fmaxf((acc[t][0] - muA) * rsA * gg.x + bt.x, 0.f);
            float yA1 = fmaxf((acc[t][1] - muA) * rsA * gg.y + bt.y, 0.f);
            float yB0 = fmaxf((acc[t][2] - muB) * rsB * gg.x + bt.x, 0.f);
            float yB1 = fmaxf((acc[t][3] - muB) * rsB * gg.y + bt.y, 0.f);
            *reinterpret_cast<float2*>(outA + col) = make_float2(yA0, yA1);
            *reinterpret_cast<float2*>(outB + col) = make_float2(yB0, yB1);
            // all-lane pooled max straight into smem (8-way q-duplicates collide
            // on the same word; smem atomic HW serializes; max is order-free)
            float p0 = fmaxf(mA ? yA0 : 0.f, mB ? yB0 : 0.f);
            float p1 = fmaxf(mA ? yA1 : 0.f, mB ? yB1 : 0.f);
            atomicMax(&gsm[col],     __float_as_int(p0));
            atomicMax(&gsm[col + 1], __float_as_int(p1));
        }
    }
    __syncthreads();

    if (tid < 128)
        gout[(size_t)n * Hdim + tid] = __int_as_float(gsm[tid]);

    // broadcast g into out[n, :, H:2H] — 16 warps x float4 lanes
    float4 gv;
    gv.x = __int_as_float(gsm[lane * 4 + 0]);
    gv.y = __int_as_float(gsm[lane * 4 + 1]);
    gv.z = __int_as_float(gsm[lane * 4 + 2]);
    gv.w = __int_as_float(gsm[lane * 4 + 3]);
    float* obase = out + (size_t)n * L * (2 * Hdim) + Hdim;
    for (int r = warp; r < L; r += 16)
        *reinterpret_cast<float4*>(obase + (size_t)r * (2 * Hdim) + lane * 4) = gv;
}

extern "C" void kernel_launch(void* const* d_in, const int* in_sizes, int n_in,
                              void* d_out, int out_size) {
    const float* x     = (const float*)d_in[0];
    const int*   mask  = (const int*)d_in[1];
    const float* W     = (const float*)d_in[2];
    const float* bias  = (const float*)d_in[3];
    const float* gamma = (const float*)d_in[4];
    const float* beta  = (const float*)d_in[5];
    float* out = (float*)d_out;

    const int NL = in_sizes[1];
    const long long ysize = (long long)NL * 2 * Hdim;
    const int N = (int)(((long long)out_size - ysize) / Hdim);
    const int L = NL / N;
    float* g = out + ysize;

    fused_kernel<<<N, 512>>>(x, mask, W, bias, gamma, beta, out, g, L);
}

// round 13
// speedup vs baseline: 1.4397x; 1.2349x over previous
#include <cuda_runtime.h>
#include <cuda_fp16.h>
#include <cstdint>

#define LN_EPS 1e-5f

static constexpr int Fdim = 64;
static constexpr int Hdim = 128;
static constexpr int SLABP = 129;   // slab row pitch (words): bank = q + 2s -> ~conflict-free

// pack two floats as fp16x2: lo -> low half, hi -> high half
__device__ __forceinline__ uint32_t packh(float lo, float hi) {
    uint32_t r;
    asm("cvt.rn.f16x2.f32 %0, %1, %2;" : "=r"(r) : "f"(hi), "f"(lo));
    return r;
}

__device__ __forceinline__ void mma_f16(float c[4], const uint32_t a[4], const uint32_t b[2]) {
    asm volatile(
        "mma.sync.aligned.m16n8k16.row.col.f32.f16.f16.f32 "
        "{%0,%1,%2,%3}, {%4,%5,%6,%7}, {%8,%9}, {%0,%1,%2,%3};\n"
        : "+f"(c[0]), "+f"(c[1]), "+f"(c[2]), "+f"(c[3])
        : "r"(a[0]), "r"(a[1]), "r"(a[2]), "r"(a[3]), "r"(b[0]), "r"(b[1]));
}

// One CTA per batch n; 16 warps x 16 rows = 256 rows/sweep, L/256 sweeps.
// fp16 GEMM -> bias -> LN -> ReLU -> write y. Pool: per-lane atomicMax into a
// q-padded smem slab (no shuffle tree, ~conflict-free). gamma/beta/bias staged
// in smem. Then slab fold -> g write + broadcast.
extern "C" __global__ void __launch_bounds__(512, 1)
fused_kernel(const float* __restrict__ x, const int* __restrict__ mask,
             const float* __restrict__ W, const float* __restrict__ bias,
             const float* __restrict__ gamma, const float* __restrict__ beta,
             float* __restrict__ out, float* __restrict__ gout, int L)
{
    __shared__ uint2  Bfrag[4 * 16 * 32];   // 16 KB
    __shared__ int    gsm8[8 * SLABP];      // pooled max slab (int bits of floats >= 0)
    __shared__ int    gsm[128];
    __shared__ float4 cgb[16][4];           // {g0, g1, b0, b1} per (t, s)
    __shared__ float2 cb[16][4];            // bias pair per (t, s)

    const int tid = threadIdx.x;
    const int n   = blockIdx.x;

    // pack W into fp16 mma B-fragment order
    for (int idx = tid; idx < 4 * 16 * 32; idx += 512) {
        int lane = idx & 31;
        int t    = (idx >> 5) & 15;
        int ks   = idx >> 9;
        int q = lane >> 2, s = lane & 3;
        int h  = t * 8 + q;
        int f0 = ks * 16 + s * 2;
        float2 w01 = *reinterpret_cast<const float2*>(W + h * Fdim + f0);
        float2 w89 = *reinterpret_cast<const float2*>(W + h * Fdim + f0 + 8);
        uint2 v;
        v.x = packh(w01.x, w01.y);
        v.y = packh(w89.x, w89.y);
        Bfrag[idx] = v;
    }
    // stage gamma/beta/bias (64 (t,s) pairs)
    if (tid < 64) {
        int t = tid >> 2, s = tid & 3;
        int col = t * 8 + 2 * s;
        float2 g2 = *reinterpret_cast<const float2*>(gamma + col);
        float2 b2 = *reinterpret_cast<const float2*>(beta  + col);
        cgb[t][s] = make_float4(g2.x, g2.y, b2.x, b2.y);
        cb[t][s]  = *reinterpret_cast<const float2*>(bias + col);
    }
    for (int i = tid; i < 8 * SLABP; i += 512) gsm8[i] = 0;
    __syncthreads();

    const int lane = tid & 31;
    const int warp = tid >> 5;
    const int q = lane >> 2, s = lane & 3;
    int* slab = gsm8 + q * SLABP;

    for (int rb = warp * 16; rb < L; rb += 256) {
        const size_t rowA = (size_t)n * L + rb + q;
        const size_t rowB = rowA + 8;
        const float* xA = x + rowA * Fdim;
        const float* xB = x + rowB * Fdim;

        float acc[16][4];
        #pragma unroll
        for (int t = 0; t < 16; t++)
            acc[t][0] = acc[t][1] = acc[t][2] = acc[t][3] = 0.f;

        #pragma unroll
        for (int ks = 0; ks < 4; ks++) {
            const int f0 = ks * 16 + s * 2;
            float2 A0 = *reinterpret_cast<const float2*>(xA + f0);
            float2 A8 = *reinterpret_cast<const float2*>(xA + f0 + 8);
            float2 B0 = *reinterpret_cast<const float2*>(xB + f0);
            float2 B8 = *reinterpret_cast<const float2*>(xB + f0 + 8);
            uint32_t ah[4] = { packh(A0.x, A0.y), packh(B0.x, B0.y),
                               packh(A8.x, A8.y), packh(B8.x, B8.y) };
            const uint2* Bp = Bfrag + ks * 512 + lane;
            #pragma unroll
            for (int t = 0; t < 16; t++) {
                uint2 bv = Bp[t * 32];
                uint32_t bh[2] = { bv.x, bv.y };
                mma_f16(acc[t], ah, bh);
            }
        }

        // bias from smem
        #pragma unroll
        for (int t = 0; t < 16; t++) {
            float2 bb = cb[t][s];
            acc[t][0] += bb.x; acc[t][1] += bb.y;
            acc[t][2] += bb.x; acc[t][3] += bb.y;
        }

        float sumA = 0.f, sqA = 0.f, sumB = 0.f, sqB = 0.f;
        #pragma unroll
        for (int t = 0; t < 16; t++) {
            sumA += acc[t][0] + acc[t][1];
            sqA  += acc[t][0] * acc[t][0] + acc[t][1] * acc[t][1];
            sumB += acc[t][2] + acc[t][3];
            sqB  += acc[t][2] * acc[t][2] + acc[t][3] * acc[t][3];
        }
        #pragma unroll
        for (int m = 1; m <= 2; m <<= 1) {
            sumA += __shfl_xor_sync(0xffffffffu, sumA, m);
            sqA  += __shfl_xor_sync(0xffffffffu, sqA, m);
            sumB += __shfl_xor_sync(0xffffffffu, sumB, m);
            sqB  += __shfl_xor_sync(0xffffffffu, sqB, m);
        }
        const float inv = 1.0f / (float)Hdim;
        float muA = sumA * inv, muB = sumB * inv;
        float rsA = rsqrtf(fmaxf(sqA * inv - muA * muA, 0.f) + LN_EPS);
        float rsB = rsqrtf(fmaxf(sqB * inv - muB * muB, 0.f) + LN_EPS);

        const bool mA = (mask[rowA] != 0);
        const bool mB = (mask[rowB] != 0);
        float* outA = out + rowA * (2 * Hdim);
        float* outB = out + rowB * (2 * Hdim);

        #pragma unroll
        for (int t = 0; t < 16; t++) {
            int col = t * 8 + 2 * s;
            float4 gb = cgb[t][s];
            float yA0 = fmaxf((acc[t][0] - muA) * rsA * gb.x + gb.z, 0.f);
            float yA1 = fmaxf((acc[t][1] - muA) * rsA * gb.y + gb.w, 0.f);
            float yB0 = fmaxf((acc[t][2] - muB) * rsB * gb.x + gb.z, 0.f);
            float yB1 = fmaxf((acc[t][3] - muB) * rsB * gb.y + gb.w, 0.f);
            *reinterpret_cast<float2*>(outA + col) = make_float2(yA0, yA1);
            *reinterpret_cast<float2*>(outB + col) = make_float2(yB0, yB1);
            // per-lane pooled max into q-spread slab row (bank = q + 2s: ~no conflicts)
            float p0 = fmaxf(mA ? yA0 : 0.f, mB ? yB0 : 0.f);
            float p1 = fmaxf(mA ? yA1 : 0.f, mB ? yB1 : 0.f);
            atomicMax(slab + col,     __float_as_int(p0));
            atomicMax(slab + col + 1, __float_as_int(p1));
        }
    }
    __syncthreads();

    // fold the 8 q-rows of the slab -> g
    if (tid < 128) {
        int m = gsm8[tid];
        #pragma unroll
        for (int k = 1; k < 8; k++) m = max(m, gsm8[k * SLABP + tid]);
        gsm[tid] = m;
        gout[(size_t)n * Hdim + tid] = __int_as_float(m);
    }
    __syncthreads();

    // broadcast g into out[n, :, H:2H] — 16 warps x float4 lanes
    float4 gv;
    gv.x = __int_as_float(gsm[lane * 4 + 0]);
    gv.y = __int_as_float(gsm[lane * 4 + 1]);
    gv.z = __int_as_float(gsm[lane * 4 + 2]);
    gv.w = __int_as_float(gsm[lane * 4 + 3]);
    float* obase = out + (size_t)n * L * (2 * Hdim) + Hdim;
    for (int r = warp; r < L; r += 16)
        *reinterpret_cast<float4*>(obase + (size_t)r * (2 * Hdim) + lane * 4) = gv;
}

extern "C" void kernel_launch(void* const* d_in, const int* in_sizes, int n_in,
                              void* d_out, int out_size) {
    const float* x     = (const float*)d_in[0];
    const int*   mask  = (const int*)d_in[1];
    const float* W     = (const float*)d_in[2];
    const float* bias  = (const float*)d_in[3];
    const float* gamma = (const float*)d_in[4];
    const float* beta  = (const float*)d_in[5];
    float* out = (float*)d_out;

    const int NL = in_sizes[1];
    const long long ysize = (long long)NL * 2 * Hdim;
    const int N = (int)(((long long)out_size - ysize) / Hdim);
    const int L = NL / N;
    float* g = out + ysize;

    fused_kernel<<<N, 512>>>(x, mask, W, bias, gamma, beta, out, g, L);
}

// round 15
// speedup vs baseline: 1.4804x; 1.0283x over previous
#include <cuda_runtime.h>
#include <cuda_fp16.h>
#include <cstdint>

#define LN_EPS 1e-5f

static constexpr int Fdim = 64;
static constexpr int Hdim = 128;
static constexpr int SLABP = 129;   // slab row pitch (words): bank = q + 2s -> ~conflict-free

// cross-CTA combine scratch (written every launch before read; counter self-resets)
__device__ int d_partial[1024][128];
__device__ int d_counter[512];

// pack two floats as fp16x2: lo -> low half, hi -> high half
__device__ __forceinline__ uint32_t packh(float lo, float hi) {
    uint32_t r;
    asm("cvt.rn.f16x2.f32 %0, %1, %2;" : "=r"(r) : "f"(hi), "f"(lo));
    return r;
}

__device__ __forceinline__ void mma_f16(float c[4], const uint32_t a[4], const uint32_t b[2]) {
    asm volatile(
        "mma.sync.aligned.m16n8k16.row.col.f32.f16.f16.f32 "
        "{%0,%1,%2,%3}, {%4,%5,%6,%7}, {%8,%9}, {%0,%1,%2,%3};\n"
        : "+f"(c[0]), "+f"(c[1]), "+f"(c[2]), "+f"(c[3])
        : "r"(a[0]), "r"(a[1]), "r"(a[2]), "r"(a[3]), "r"(b[0]), "r"(b[1]));
}

// grid = 2N: CTA (n, half) owns 256 rows; 8 warps x 16 rows x 2 sweeps.
// Warp tile identical to R13 champion (16 rows x 128 cols). 2 CTAs/SM.
// fp16 GEMM (acc initialized with bias) -> LN -> ReLU -> y; pool via q-slab
// atomicMax; cross-CTA combine via d_partial; last arriver writes g + broadcast.
extern "C" __global__ void __launch_bounds__(256, 2)
fused_kernel(const float* __restrict__ x, const int* __restrict__ mask,
             const float* __restrict__ W, const float* __restrict__ bias,
             const float* __restrict__ gamma, const float* __restrict__ beta,
             float* __restrict__ out, float* __restrict__ gout, int L)
{
    __shared__ uint4  Bfrag[4 * 8 * 32];    // [ks][tpair][lane] = {t0.x,t0.y,t1.x,t1.y}
    __shared__ int    gsm8[8 * SLABP];      // pooled max slab (int bits of floats >= 0)
    __shared__ int    gsm[128];
    __shared__ float4 cgb[16][4];           // {g0, g1, b0, b1} per (t, s)
    __shared__ float2 cb[16][4];            // bias pair per (t, s)
    __shared__ int    sIsLast;

    const int tid  = threadIdx.x;
    const int bidx = blockIdx.x;
    const int n    = bidx >> 1;
    const int half = bidx & 1;

    // pack W into paired fp16 mma B-fragment order
    for (int idx = tid; idx < 4 * 8 * 32; idx += 256) {
        int lane = idx & 31;
        int tp   = (idx >> 5) & 7;
        int ks   = idx >> 8;
        int q = lane >> 2, s = lane & 3;
        int f0 = ks * 16 + s * 2;
        int h0 = (2 * tp) * 8 + q;
        int h1 = (2 * tp + 1) * 8 + q;
        float2 a01 = *reinterpret_cast<const float2*>(W + h0 * Fdim + f0);
        float2 a89 = *reinterpret_cast<const float2*>(W + h0 * Fdim + f0 + 8);
        float2 b01 = *reinterpret_cast<const float2*>(W + h1 * Fdim + f0);
        float2 b89 = *reinterpret_cast<const float2*>(W + h1 * Fdim + f0 + 8);
        uint4 v;
        v.x = packh(a01.x, a01.y);
        v.y = packh(a89.x, a89.y);
        v.z = packh(b01.x, b01.y);
        v.w = packh(b89.x, b89.y);
        Bfrag[idx] = v;
    }
    // stage gamma/beta/bias (64 (t,s) pairs)
    if (tid < 64) {
        int t = tid >> 2, s = tid & 3;
        int col = t * 8 + 2 * s;
        float2 g2 = *reinterpret_cast<const float2*>(gamma + col);
        float2 b2 = *reinterpret_cast<const float2*>(beta  + col);
        cgb[t][s] = make_float4(g2.x, g2.y, b2.x, b2.y);
        cb[t][s]  = *reinterpret_cast<const float2*>(bias + col);
    }
    for (int i = tid; i < 8 * SLABP; i += 256) gsm8[i] = 0;
    __syncthreads();

    const int lane = tid & 31;
    const int warp = tid >> 5;
    const int q = lane >> 2, s = lane & 3;
    int* slab = gsm8 + q * SLABP;

    const int rbeg = half * 256;
    for (int rb = rbeg + warp * 16; rb < rbeg + 256; rb += 128) {
        const size_t rowA = (size_t)n * L + rb + q;
        const size_t rowB = rowA + 8;
        const float* xA = x + rowA * Fdim;
        const float* xB = x + rowB * Fdim;

        // acc initialized with bias (folds the post-GEMM bias add into init)
        float acc[16][4];
        #pragma unroll
        for (int t = 0; t < 16; t++) {
            float2 bb = cb[t][s];
            acc[t][0] = bb.x; acc[t][1] = bb.y;
            acc[t][2] = bb.x; acc[t][3] = bb.y;
        }

        #pragma unroll
        for (int ks = 0; ks < 4; ks++) {
            const int f0 = ks * 16 + s * 2;
            float2 A0 = *reinterpret_cast<const float2*>(xA + f0);
            float2 A8 = *reinterpret_cast<const float2*>(xA + f0 + 8);
            float2 B0 = *reinterpret_cast<const float2*>(xB + f0);
            float2 B8 = *reinterpret_cast<const float2*>(xB + f0 + 8);
            uint32_t ah[4] = { packh(A0.x, A0.y), packh(B0.x, B0.y),
                               packh(A8.x, A8.y), packh(B8.x, B8.y) };
            const uint4* Bp = Bfrag + ks * 256 + lane;
            #pragma unroll
            for (int tp = 0; tp < 8; tp++) {
                uint4 bv = Bp[tp * 32];
                uint32_t bh0[2] = { bv.x, bv.y };
                uint32_t bh1[2] = { bv.z, bv.w };
                mma_f16(acc[2 * tp],     ah, bh0);
                mma_f16(acc[2 * tp + 1], ah, bh1);
            }
        }

        float sumA = 0.f, sqA = 0.f, sumB = 0.f, sqB = 0.f;
        #pragma unroll
        for (int t = 0; t < 16; t++) {
            sumA += acc[t][0] + acc[t][1];
            sqA  += acc[t][0] * acc[t][0] + acc[t][1] * acc[t][1];
            sumB += acc[t][2] + acc[t][3];
            sqB  += acc[t][2] * acc[t][2] + acc[t][3] * acc[t][3];
        }
        #pragma unroll
        for (int m = 1; m <= 2; m <<= 1) {
            sumA += __shfl_xor_sync(0xffffffffu, sumA, m);
            sqA  += __shfl_xor_sync(0xffffffffu, sqA, m);
            sumB += __shfl_xor_sync(0xffffffffu, sumB, m);
            sqB  += __shfl_xor_sync(0xffffffffu, sqB, m);
        }
        const float inv = 1.0f / (float)Hdim;
        float muA = sumA * inv, muB = sumB * inv;
        float rsA = rsqrtf(fmaxf(sqA * inv - muA * muA, 0.f) + LN_EPS);
        float rsB = rsqrtf(fmaxf(sqB * inv - muB * muB, 0.f) + LN_EPS);

        const bool mA = (mask[rowA] != 0);
        const bool mB = (mask[rowB] != 0);
        float* outA = out + rowA * (2 * Hdim);
        float* outB = out + rowB * (2 * Hdim);

        #pragma unroll
        for (int t = 0; t < 16; t++) {
            int col = t * 8 + 2 * s;
            float4 gb = cgb[t][s];
            float yA0 = fmaxf((acc[t][0] - muA) * rsA * gb.x + gb.z, 0.f);
            float yA1 = fmaxf((acc[t][1] - muA) * rsA * gb.y + gb.w, 0.f);
            float yB0 = fmaxf((acc[t][2] - muB) * rsB * gb.x + gb.z, 0.f);
            float yB1 = fmaxf((acc[t][3] - muB) * rsB * gb.y + gb.w, 0.f);
            *reinterpret_cast<float2*>(outA + col) = make_float2(yA0, yA1);
            *reinterpret_cast<float2*>(outB + col) = make_float2(yB0, yB1);
            float p0 = fmaxf(mA ? yA0 : 0.f, mB ? yB0 : 0.f);
            float p1 = fmaxf(mA ? yA1 : 0.f, mB ? yB1 : 0.f);
            atomicMax(slab + col,     __float_as_int(p0));
            atomicMax(slab + col + 1, __float_as_int(p1));
        }
    }
    __syncthreads();

    // fold the 8 q-rows of the slab -> per-CTA partial; publish
    if (tid < 128) {
        int m = gsm8[tid];
        #pragma unroll
        for (int k = 1; k < 8; k++) m = max(m, gsm8[k * SLABP + tid]);
        d_partial[bidx][tid] = m;
    }
    __threadfence();
    __syncthreads();
    if (tid == 0) sIsLast = (atomicAdd(&d_counter[n], 1) == 1);
    __syncthreads();
    if (!sIsLast) return;

    __threadfence();
    if (tid < 128) {
        const int base = n << 1;
        int c = max(d_partial[base][tid], d_partial[base + 1][tid]);
        gsm[tid] = c;
        gout[(size_t)n * Hdim + tid] = __int_as_float(c);
    }
    if (tid == 0) d_counter[n] = 0;   // self-reset for next graph replay
    __syncthreads();

    // broadcast g into out[n, :, H:2H] (whole batch, 8 warps)
    float4 gv;
    gv.x = __int_as_float(gsm[lane * 4 + 0]);
    gv.y = __int_as_float(gsm[lane * 4 + 1]);
    gv.z = __int_as_float(gsm[lane * 4 + 2]);
    gv.w = __int_as_float(gsm[lane * 4 + 3]);
    float* obase = out + (size_t)n * L * (2 * Hdim) + Hdim;
    for (int r = warp; r < L; r += 8)
        *reinterpret_cast<float4*>(obase + (size_t)r * (2 * Hdim) + lane * 4) = gv;
}

extern "C" void kernel_launch(void* const* d_in, const int* in_sizes, int n_in,
                              void* d_out, int out_size) {
    const float* x     = (const float*)d_in[0];
    const int*   mask  = (const int*)d_in[1];
    const float* W     = (const float*)d_in[2];
    const float* bias  = (const float*)d_in[3];
    const float* gamma = (const float*)d_in[4];
    const float* beta  = (const float*)d_in[5];
    float* out = (float*)d_out;

    const int NL = in_sizes[1];
    const long long ysize = (long long)NL * 2 * Hdim;
    const int N = (int)(((long long)out_size - ysize) / Hdim);
    const int L = NL / N;
    float* g = out + ysize;

    fused_kernel<<<2 * N, 256>>>(x, mask, W, bias, gamma, beta, out, g, L);
}